// round 15
// baseline (speedup 1.0000x reference)
#include <cuda_runtime.h>
#include <cuda_fp16.h>
#include <cstdint>

#define N_E    8192
#define E_DIM  256
#define N_TOK  32768

#define OFF_ZQ   0
#define OFF_IDX  8388608
#define OFF_LOSS 8421376
#define OFF_NEMB 8421377

#define TH_MARGIN 4.0e-2f
#define BM     256
#define BN     64
#define NSTG   128               // 8192 / 64

// dynamic smem layout (bytes)
#define SM_A   0u                // 256 x 528 (f16 A, all rows)   = 135168
#define SM_B   135168u           // 2 x 64 x 528 (f16 B)          = 67584
#define SM_EN  202752u           // 2 x 256B
#define SM_ZN  203264u           // 256 x 4B
#define SM_DYN 204800

// ---- device scratch (no allocations allowed) ----
__device__ float g_bins[N_E];
__device__ float g_dw[N_E * E_DIM];
__device__ float g_eN[N_E];
__device__ float g_loss;
__device__ int   g_ucount;
__device__ int   g_idxi[N_TOK];
__device__ float g_zn[N_TOK];
__device__ int   g_urows[N_TOK];
__device__ int   g_ucand[N_TOK * 32];
__device__ __half g_eh[N_E * E_DIM];

// ---------------- PTX helpers ----------------
__device__ __forceinline__ uint32_t smem_u32(const void* p) {
    uint32_t a;
    asm("{ .reg .u64 t; cvta.to.shared.u64 t, %1; cvt.u32.u64 %0, t; }" : "=r"(a) : "l"(p));
    return a;
}
__device__ __forceinline__ void cpa16(uint32_t dst, const void* src) {
    asm volatile("cp.async.cg.shared.global [%0], [%1], 16;" :: "r"(dst), "l"(src) : "memory");
}
__device__ __forceinline__ void ldm4(uint32_t* r, uint32_t a) {
    asm volatile("ldmatrix.sync.aligned.m8n8.x4.shared.b16 {%0,%1,%2,%3}, [%4];"
                 : "=r"(r[0]), "=r"(r[1]), "=r"(r[2]), "=r"(r[3]) : "r"(a));
}
__device__ __forceinline__ void mma16816(float* c, const uint32_t* a, const uint32_t* b) {
    asm volatile(
        "mma.sync.aligned.m16n8k16.row.col.f32.f16.f16.f32 "
        "{%0,%1,%2,%3}, {%4,%5,%6,%7}, {%8,%9}, {%0,%1,%2,%3};"
        : "+f"(c[0]), "+f"(c[1]), "+f"(c[2]), "+f"(c[3])
        : "r"(a[0]), "r"(a[1]), "r"(a[2]), "r"(a[3]), "r"(b[0]), "r"(b[1]));
}
__device__ __forceinline__ void lds128(uint32_t* r, uint32_t a) {
    asm volatile("ld.shared.v4.u32 {%0,%1,%2,%3}, [%4];"
                 : "=r"(r[0]), "=r"(r[1]), "=r"(r[2]), "=r"(r[3]) : "r"(a));
}

// ============================================================
// K1: zero scratch + ||e||^2 (exact sequential, matches reference rounding)
// ============================================================
__global__ void k_init(const float* __restrict__ emb) {
    int gid = blockIdx.x * blockDim.x + threadIdx.x;
    if (gid < N_E * E_DIM) g_dw[gid] = 0.0f;
    if (gid < N_E) {
        g_bins[gid] = 0.0f;
        const float* e = emb + (size_t)gid * E_DIM;
        float s = 0.0f;
        #pragma unroll 8
        for (int k = 0; k < E_DIM; k++) s = __fadd_rn(s, __fmul_rn(e[k], e[k]));
        g_eN[gid] = s;
    }
    if (gid == 0) { g_loss = 0.0f; g_ucount = 0; }
}

// ============================================================
// K2: f16 image of embeddings
// ============================================================
__global__ void k_prep(const float* __restrict__ emb) {
    int gid = blockIdx.x * blockDim.x + threadIdx.x;
    g_eh[gid] = __float2half_rn(emb[gid]);
}

// ============================================================
// K3: hybrid distance GEMM — warps 0-7 f16 HMMA (rows 0-127),
//     warps 8-15 HFMA2 SIMT (rows 128-255); shared f16 B image.
//     ALL 512 threads run prefetchB every stage.
// ============================================================
__device__ __forceinline__ void prefetchB(uint32_t sb, int tid, int nt) {
    int s = nt & 1;
    int row = tid >> 3;                  // 0..63
    int q   = tid & 7;
    const char* src = (const char*)g_eh + ((size_t)nt * BN + row) * 512 + (size_t)q * 64;
    uint32_t dst = sb + SM_B + (uint32_t)s * 33792u + (uint32_t)row * 528u + (uint32_t)q * 64;
    #pragma unroll
    for (int j = 0; j < 4; j++) cpa16(dst + j * 16, src + j * 16);
    if (tid < 16) cpa16(sb + SM_EN + (uint32_t)s * 256 + tid * 16,
                        (const char*)g_eN + (size_t)nt * 256 + tid * 16);
}

__global__ __launch_bounds__(512, 1)
void k_mma(const float* __restrict__ z) {
    extern __shared__ char smraw[];
    const uint32_t sb = smem_u32(smraw);
    const int tid  = threadIdx.x;
    const int lane = tid & 31;
    const int wid  = tid >> 5;           // 0..15
    const int row0 = blockIdx.x * BM;

    prefetchB(sb, tid, 0);
    asm volatile("cp.async.commit_group;" ::: "memory");

    // ---- prologue: all 256 rows -> f16 A in smem, exact zn ----
    if (tid < BM) {
        const float4* zr4 = (const float4*)(z + (size_t)(row0 + tid) * E_DIM);
        uint32_t* ap = (uint32_t*)(smraw + SM_A + (uint32_t)tid * 528u);
        float zn = 0.0f;
        #pragma unroll 4
        for (int i = 0; i < 64; i++) {
            float4 v = zr4[i];
            zn = __fadd_rn(zn, __fmul_rn(v.x, v.x));
            zn = __fadd_rn(zn, __fmul_rn(v.y, v.y));
            zn = __fadd_rn(zn, __fmul_rn(v.z, v.z));
            zn = __fadd_rn(zn, __fmul_rn(v.w, v.w));
            __half h0 = __float2half_rn(v.x), h1 = __float2half_rn(v.y);
            __half h2 = __float2half_rn(v.z), h3 = __float2half_rn(v.w);
            ap[i * 2 + 0] = ((uint32_t)__half_as_ushort(h1) << 16) | __half_as_ushort(h0);
            ap[i * 2 + 1] = ((uint32_t)__half_as_ushort(h3) << 16) | __half_as_ushort(h2);
        }
        *(float*)(smraw + SM_ZN + tid * 4) = zn;
        g_zn[row0 + tid] = zn;
    }
    __syncthreads();

    if (wid < 8) {
        // ================= HMMA half: rows wid*16 .. wid*16+15 =================
        const int gid = lane >> 2;
        const int tig = lane & 3;
        uint32_t aA = sb + SM_A + ((uint32_t)(wid * 16) + (uint32_t)(lane & 15)) * 528u
                    + ((uint32_t)(lane >> 4) & 1) * 16;
        uint32_t bA[4];
        #pragma unroll
        for (int p = 0; p < 4; p++)
            bA[p] = sb + SM_B + ((uint32_t)(p * 16) + (uint32_t)(lane & 15)) * 528u
                  + ((uint32_t)(lane >> 4) & 1) * 16;
        float zn0 = *(const float*)(smraw + SM_ZN + (wid * 16 + gid) * 4);
        float zn1 = *(const float*)(smraw + SM_ZN + (wid * 16 + gid + 8) * 4);

        float tb0[2][2];
        int   ti0[2][2];
        #pragma unroll
        for (int s2 = 0; s2 < 2; s2++) { tb0[s2][0] = 3.4e38f; tb0[s2][1] = 3.4e38f; ti0[s2][0] = 0; ti0[s2][1] = 0; }

        for (int nt = 0; nt < NSTG; nt++) {
            if (nt + 1 < NSTG) {
                prefetchB(sb, tid, nt + 1);
                asm volatile("cp.async.commit_group;" ::: "memory");
                asm volatile("cp.async.wait_group 1;" ::: "memory");
            } else {
                asm volatile("cp.async.wait_group 0;" ::: "memory");
            }
            __syncthreads();

            const uint32_t sof = (uint32_t)(nt & 1) * 33792u;
            float acc[8][4];
            #pragma unroll
            for (int f = 0; f < 8; f++)
                #pragma unroll
                for (int q = 0; q < 4; q++) acc[f][q] = 0.0f;

            #pragma unroll
            for (int kk = 0; kk < 16; kk++) {
                uint32_t kb = (uint32_t)kk * 32;
                uint32_t af[4], bw[4][4];
                ldm4(af, aA + kb);
                #pragma unroll
                for (int p = 0; p < 4; p++) ldm4(bw[p], bA[p] + sof + kb);
                #pragma unroll
                for (int p = 0; p < 4; p++)
                    #pragma unroll
                    for (int q = 0; q < 2; q++) {
                        uint32_t bf[2] = { bw[p][q], bw[p][q + 2] };
                        mma16816(acc[p * 2 + q], af, bf);
                    }
            }

            const float* eNs = (const float*)(smraw + SM_EN + (uint32_t)(nt & 1) * 256);
            #pragma unroll
            for (int f = 0; f < 8; f++) {
                int colb = nt * BN + f * 8 + 2 * tig;
                float e0 = eNs[f * 8 + 2 * tig];
                float e1 = eNs[f * 8 + 2 * tig + 1];
                float d00 = __fmaf_rn(-2.0f, acc[f][0], zn0 + e0);
                float d01 = __fmaf_rn(-2.0f, acc[f][1], zn0 + e1);
                float d10 = __fmaf_rn(-2.0f, acc[f][2], zn1 + e0);
                float d11 = __fmaf_rn(-2.0f, acc[f][3], zn1 + e1);
                if (d00 < tb0[0][1]) { if (d00 < tb0[0][0]) { tb0[0][1]=tb0[0][0]; ti0[0][1]=ti0[0][0]; tb0[0][0]=d00; ti0[0][0]=colb; } else { tb0[0][1]=d00; ti0[0][1]=colb; } }
                if (d01 < tb0[0][1]) { if (d01 < tb0[0][0]) { tb0[0][1]=tb0[0][0]; ti0[0][1]=ti0[0][0]; tb0[0][0]=d01; ti0[0][0]=colb+1; } else { tb0[0][1]=d01; ti0[0][1]=colb+1; } }
                if (d10 < tb0[1][1]) { if (d10 < tb0[1][0]) { tb0[1][1]=tb0[1][0]; ti0[1][1]=ti0[1][0]; tb0[1][0]=d10; ti0[1][0]=colb; } else { tb0[1][1]=d10; ti0[1][1]=colb; } }
                if (d11 < tb0[1][1]) { if (d11 < tb0[1][0]) { tb0[1][1]=tb0[1][0]; ti0[1][1]=ti0[1][0]; tb0[1][0]=d11; ti0[1][0]=colb+1; } else { tb0[1][1]=d11; ti0[1][1]=colb+1; } }
            }
            __syncthreads();
        }

        // write candidates: table [256][32] in reused A region
        float* tD = (float*)smraw;
        int*   tI = (int*)(smraw + 32768);
        int r1 = wid * 16 + gid, r2 = r1 + 8;
        tD[r1 * 32 + tig * 2 + 0] = tb0[0][0]; tI[r1 * 32 + tig * 2 + 0] = ti0[0][0];
        tD[r1 * 32 + tig * 2 + 1] = tb0[0][1]; tI[r1 * 32 + tig * 2 + 1] = ti0[0][1];
        tD[r2 * 32 + tig * 2 + 0] = tb0[1][0]; tI[r2 * 32 + tig * 2 + 0] = ti0[1][0];
        tD[r2 * 32 + tig * 2 + 1] = tb0[1][1]; tI[r2 * 32 + tig * 2 + 1] = ti0[1][1];
    } else {
        // ================= HFMA2 half: rows 128 + (wid-8)*16 .. +15 =================
        const int sw = wid - 8;
        const int rl = lane >> 3;         // 0..3
        const int cl = lane & 7;          // 0..7
        const int arow0 = sw * 16 + rl * 4;    // local row base within [0,128)
        float znv[4];
        #pragma unroll
        for (int rr = 0; rr < 4; rr++)
            znv[rr] = *(const float*)(smraw + SM_ZN + (128 + arow0 + rr) * 4);
        uint32_t aAd[4];
        #pragma unroll
        for (int rr = 0; rr < 4; rr++)
            aAd[rr] = sb + SM_A + (uint32_t)(128 + arow0 + rr) * 528u;
        uint32_t bBase = sb + SM_B + (uint32_t)cl * 528u;

        float tb[4][4];
        int   ti[4][4];
        #pragma unroll
        for (int rr = 0; rr < 4; rr++)
            #pragma unroll
            for (int t = 0; t < 4; t++) { tb[rr][t] = 3.4e38f; ti[rr][t] = 0; }

        const __half2 hz = __float2half2_rn(0.0f);

        for (int nt = 0; nt < NSTG; nt++) {
            if (nt + 1 < NSTG) {
                prefetchB(sb, tid, nt + 1);
                asm volatile("cp.async.commit_group;" ::: "memory");
                asm volatile("cp.async.wait_group 1;" ::: "memory");
            } else {
                asm volatile("cp.async.wait_group 0;" ::: "memory");
            }
            __syncthreads();

            const uint32_t sof = (uint32_t)(nt & 1) * 33792u;
            __half2 acc[4][8];
            #pragma unroll
            for (int rr = 0; rr < 4; rr++)
                #pragma unroll
                for (int j = 0; j < 8; j++) acc[rr][j] = hz;

            #pragma unroll 4
            for (int ck = 0; ck < 32; ck++) {
                uint32_t kb = (uint32_t)ck * 16;
                uint32_t a4[4][4];
                #pragma unroll
                for (int rr = 0; rr < 4; rr++) lds128(a4[rr], aAd[rr] + kb);
                #pragma unroll
                for (int j = 0; j < 8; j++) {
                    uint32_t b4[4];
                    lds128(b4, bBase + sof + (uint32_t)j * (8u * 528u) + kb);
                    #pragma unroll
                    for (int rr = 0; rr < 4; rr++) {
                        acc[rr][j] = __hfma2(*(__half2*)&a4[rr][0], *(__half2*)&b4[0], acc[rr][j]);
                        acc[rr][j] = __hfma2(*(__half2*)&a4[rr][1], *(__half2*)&b4[1], acc[rr][j]);
                        acc[rr][j] = __hfma2(*(__half2*)&a4[rr][2], *(__half2*)&b4[2], acc[rr][j]);
                        acc[rr][j] = __hfma2(*(__half2*)&a4[rr][3], *(__half2*)&b4[3], acc[rr][j]);
                    }
                }
            }

            const float* eNs = (const float*)(smraw + SM_EN + (uint32_t)(nt & 1) * 256);
            #pragma unroll
            for (int j = 0; j < 8; j++) {
                int cc = cl + 8 * j;
                int col = nt * BN + cc;
                float ec = eNs[cc];
                #pragma unroll
                for (int rr = 0; rr < 4; rr++) {
                    float dot = __fadd_rn(__half2float(__low2half(acc[rr][j])),
                                          __half2float(__high2half(acc[rr][j])));
                    float d = __fmaf_rn(-2.0f, dot, znv[rr] + ec);
                    if (d < tb[rr][3]) {
                        if (d < tb[rr][2]) {
                            tb[rr][3] = tb[rr][2]; ti[rr][3] = ti[rr][2];
                            if (d < tb[rr][1]) {
                                tb[rr][2] = tb[rr][1]; ti[rr][2] = ti[rr][1];
                                if (d < tb[rr][0]) {
                                    tb[rr][1] = tb[rr][0]; ti[rr][1] = ti[rr][0];
                                    tb[rr][0] = d; ti[rr][0] = col;
                                } else { tb[rr][1] = d; ti[rr][1] = col; }
                            } else { tb[rr][2] = d; ti[rr][2] = col; }
                        } else { tb[rr][3] = d; ti[rr][3] = col; }
                    }
                }
            }
            __syncthreads();
        }

        float* tD = (float*)smraw;
        int*   tI = (int*)(smraw + 32768);
        #pragma unroll
        for (int rr = 0; rr < 4; rr++) {
            int r = 128 + arow0 + rr;
            #pragma unroll
            for (int t = 0; t < 4; t++) {
                tD[r * 32 + cl * 4 + t] = tb[rr][t];
                tI[r * 32 + cl * 4 + t] = ti[rr][t];
            }
        }
    }
    __syncthreads();

    // ---- merge per row ----
    if (tid < BM) {
        float* tD = (float*)smraw;
        int*   tI = (int*)(smraw + 32768);
        int nq = (tid < 128) ? 8 : 32;
        float b0 = 3.4e38f, b1 = 3.4e38f;
        int   i0 = 0x7FFFFFFF, i1 = 0x7FFFFFFF;
        for (int q = 0; q < nq; q++) {
            float d = tD[tid * 32 + q];
            int   c = tI[tid * 32 + q];
            if (d < b0 || (d == b0 && c < i0)) { b1 = b0; i1 = i0; b0 = d; i0 = c; }
            else if (d < b1 || (d == b1 && c < i1)) { b1 = d; i1 = c; }
        }
        int r = row0 + tid;
        g_idxi[r] = i0;
        if (__fsub_rn(b1, b0) < TH_MARGIN) {
            int u = atomicAdd(&g_ucount, 1);
            g_urows[u] = r;
            for (int q = 0; q < 32; q++)
                g_ucand[u * 32 + q] = tI[tid * 32 + (q < nq ? q : 0)];
        }
    }
}

// ============================================================
// K4: exact rescore of flagged rows (R0-identical numerics), 32 candidates
// ============================================================
__global__ void k_rescore(const float* __restrict__ z, const float* __restrict__ emb) {
    int t = blockIdx.x * blockDim.x + threadIdx.x;
    if (t >= g_ucount) return;
    int r = g_urows[t];
    const float* zr = z + (size_t)r * E_DIM;
    float zn = g_zn[r];
    float bd = 3.4e38f;
    int   bi = 0x7FFFFFFF;
    #pragma unroll 1
    for (int q = 0; q < 32; q++) {
        int c = g_ucand[t * 32 + q];
        const float* er = emb + (size_t)c * E_DIM;
        float acc = 0.0f;
        #pragma unroll 8
        for (int k = 0; k < E_DIM; k++) acc = __fmaf_rn(zr[k], er[k], acc);
        float d = __fsub_rn(__fadd_rn(zn, g_eN[c]), __fmul_rn(2.0f, acc));
        if (d < bd || (d == bd && c < bi)) { bd = d; bi = c; }
    }
    g_idxi[r] = bi;
}

// ============================================================
// K5: epilogue — z_q/straight-through, loss partials, bins/dw atomics
// ============================================================
__global__ __launch_bounds__(256)
void k_epi(const float* __restrict__ z, const float* __restrict__ emb,
           float* __restrict__ out_zq, float* __restrict__ out_idx) {
    __shared__ float sl[256];
    int tid = threadIdx.x;
    int row0 = blockIdx.x * 128;
    int r = row0 + (tid >> 1);
    int h = tid & 1;
    int bi = g_idxi[r];
    if (h == 0) { out_idx[r] = (float)bi; atomicAdd(&g_bins[bi], 1.0f); }
    const float4* zr = (const float4*)(z + (size_t)r * E_DIM + h * 128);
    const float4* er = (const float4*)(emb + (size_t)bi * E_DIM + h * 128);
    float4* oq = (float4*)(out_zq + (size_t)r * E_DIM + h * 128);
    float* dw = g_dw + (size_t)bi * E_DIM + h * 128;
    float ls = 0.0f;
    #pragma unroll 4
    for (int d4 = 0; d4 < 32; d4++) {
        float4 zv = zr[d4];
        float4 ev = er[d4];
        float4 o;
        o.x = __fadd_rn(zv.x, __fsub_rn(ev.x, zv.x));
        o.y = __fadd_rn(zv.y, __fsub_rn(ev.y, zv.y));
        o.z = __fadd_rn(zv.z, __fsub_rn(ev.z, zv.z));
        o.w = __fadd_rn(zv.w, __fsub_rn(ev.w, zv.w));
        oq[d4] = o;
        float dx = __fsub_rn(zv.x, ev.x);
        float dy = __fsub_rn(zv.y, ev.y);
        float dz = __fsub_rn(zv.z, ev.z);
        float dwv = __fsub_rn(zv.w, ev.w);
        ls = __fadd_rn(ls, __fmul_rn(dx, dx));
        ls = __fadd_rn(ls, __fmul_rn(dy, dy));
        ls = __fadd_rn(ls, __fmul_rn(dz, dz));
        ls = __fadd_rn(ls, __fmul_rn(dwv, dwv));
        atomicAdd(dw + d4 * 4 + 0, zv.x);
        atomicAdd(dw + d4 * 4 + 1, zv.y);
        atomicAdd(dw + d4 * 4 + 2, zv.z);
        atomicAdd(dw + d4 * 4 + 3, zv.w);
    }
    sl[tid] = ls;
    __syncthreads();
    for (int s = 128; s > 0; s >>= 1) {
        if (tid < s) sl[tid] += sl[tid + s];
        __syncthreads();
    }
    if (tid == 0) atomicAdd(&g_loss, sl[0]);
}

// ============================================================
// K6: finalize new_embeddings + loss
// ============================================================
__global__ void k_final(float* __restrict__ out_nemb, float* __restrict__ out_loss) {
    int gid = blockIdx.x * blockDim.x + threadIdx.x;
    if (gid == 0) {
        float mean = __fdiv_rn(g_loss, 8388608.0f);
        out_loss[0] = __fmul_rn(0.25f, mean);
    }
    if (gid < N_E * E_DIM) {
        int k = gid >> 8;
        float b = g_bins[k];
        float t1 = __fadd_rn(b, 1e-5f);
        float cl = __fmul_rn(__fdiv_rn(t1, 32768.08192f), 32768.0f);
        out_nemb[gid] = __fdiv_rn(g_dw[gid], cl);
    }
}

// ============================================================
extern "C" void kernel_launch(void* const* d_in, const int* in_sizes, int n_in,
                              void* d_out, int out_size) {
    const float* z   = (const float*)d_in[0];
    const float* emb = (const float*)d_in[1];
    float* out = (float*)d_out;

    cudaFuncSetAttribute(k_mma, cudaFuncAttributeMaxDynamicSharedMemorySize, SM_DYN);

    k_init<<<8192, 256>>>(emb);
    k_prep<<<8192, 256>>>(emb);
    k_mma<<<N_TOK / BM, 512, SM_DYN>>>(z);
    k_rescore<<<256, 256>>>(z, emb);
    k_epi<<<N_TOK / 128, 256>>>(z, emb, out + OFF_ZQ, out + OFF_IDX);
    k_final<<<8192, 256>>>(out + OFF_NEMB, out + OFF_LOSS);
}

// round 16
// speedup vs baseline: 2.3331x; 2.3331x over previous
#include <cuda_runtime.h>
#include <cuda_fp16.h>
#include <cstdint>

#define N_E    8192
#define E_DIM  256
#define N_TOK  32768

#define OFF_ZQ   0
#define OFF_IDX  8388608
#define OFF_LOSS 8421376
#define OFF_NEMB 8421377

#define TH_MARGIN 1.0e-2f
#define BM     256
#define BN     64
#define NSTG   128               // 8192 / 64
#define ROWSTR 528u              // padded fp16 row stride bytes (256*2 + 16)

// dynamic smem layout (bytes)
#define SM_A   0u                // 256 x 528 = 135168
#define SM_B   135168u           // 2 stages x 64 x 528 = 67584
#define SM_EN  202752u           // 2 stages x 256B
#define SM_ZN  203264u           // 256 x 4B
#define SM_DYN 204800

// ---- device scratch (no allocations allowed) ----
__device__ float g_bins[N_E];
__device__ float g_dw[N_E * E_DIM];
__device__ float g_eN[N_E];
__device__ float g_loss;
__device__ int   g_ucount;
__device__ int   g_idxi[N_TOK];
__device__ float g_zn[N_TOK];
__device__ int   g_urows[N_TOK];
__device__ int   g_ucand[N_TOK * 16];
__device__ __half g_eh[N_E * E_DIM];

// ---------------- PTX helpers ----------------
__device__ __forceinline__ uint32_t smem_u32(const void* p) {
    uint32_t a;
    asm("{ .reg .u64 t; cvta.to.shared.u64 t, %1; cvt.u32.u64 %0, t; }" : "=r"(a) : "l"(p));
    return a;
}
__device__ __forceinline__ void cpa16(uint32_t dst, const void* src) {
    asm volatile("cp.async.cg.shared.global [%0], [%1], 16;" :: "r"(dst), "l"(src) : "memory");
}
__device__ __forceinline__ void ldm4(uint32_t* r, uint32_t a) {
    asm volatile("ldmatrix.sync.aligned.m8n8.x4.shared.b16 {%0,%1,%2,%3}, [%4];"
                 : "=r"(r[0]), "=r"(r[1]), "=r"(r[2]), "=r"(r[3]) : "r"(a));
}
// fp16-accumulator HMMA: D(f16x2 x2) = A x B + C
__device__ __forceinline__ void mma16816h(uint32_t* c, const uint32_t* a, const uint32_t* b) {
    asm volatile(
        "mma.sync.aligned.m16n8k16.row.col.f16.f16.f16.f16 "
        "{%0,%1}, {%2,%3,%4,%5}, {%6,%7}, {%0,%1};"
        : "+r"(c[0]), "+r"(c[1])
        : "r"(a[0]), "r"(a[1]), "r"(a[2]), "r"(a[3]), "r"(b[0]), "r"(b[1]));
}

// ============================================================
// K1 (fused init+prep): zero g_dw, f16 image (coalesced), ||e||^2 exact,
// scalar-sequential rounding preserved via in-order float4 adds.
// ============================================================
__global__ void k_prep(const float* __restrict__ emb) {
    int gid = blockIdx.x * blockDim.x + threadIdx.x;     // 0 .. 2M-1
    // elementwise: zero dw, f16 convert (fully coalesced)
    g_dw[gid] = 0.0f;
    g_eh[gid] = __float2half_rn(emb[gid]);
    // per-code: bins + exact sequential ||e||^2 (float4 loads, in-order adds)
    if (gid < N_E) {
        g_bins[gid] = 0.0f;
        const float4* e4 = (const float4*)(emb + (size_t)gid * E_DIM);
        float s = 0.0f;
        #pragma unroll 8
        for (int i = 0; i < 64; i++) {
            float4 v = e4[i];
            s = __fadd_rn(s, __fmul_rn(v.x, v.x));
            s = __fadd_rn(s, __fmul_rn(v.y, v.y));
            s = __fadd_rn(s, __fmul_rn(v.z, v.z));
            s = __fadd_rn(s, __fmul_rn(v.w, v.w));
        }
        g_eN[gid] = s;
    }
    if (gid == 0) { g_loss = 0.0f; g_ucount = 0; }
}

// ============================================================
// K3: fp16 mma.sync (f16 acc) distance GEMM + top-2 + margin flag
//   CTA: 256 z-rows x all 8192 codes; 512 thr / 16 warps as 8M x 2N,
//   warp tile 32x32  (identical to the proven R11 kernel)
// ============================================================
__device__ __forceinline__ void prefetchB(uint32_t sb, int tid, int nt) {
    int s = nt & 1;
    int row = tid >> 3;                  // 0..63
    int q   = tid & 7;                   // 64B eighth
    const char* src = (const char*)g_eh + ((size_t)nt * BN + row) * 512 + (size_t)q * 64;
    uint32_t dst = sb + SM_B + (uint32_t)s * 33792u + (uint32_t)row * ROWSTR + (uint32_t)q * 64;
    #pragma unroll
    for (int j = 0; j < 4; j++) cpa16(dst + j * 16, src + j * 16);
    if (tid < 16) cpa16(sb + SM_EN + (uint32_t)s * 256 + tid * 16,
                        (const char*)g_eN + (size_t)nt * 256 + tid * 16);
}

__global__ __launch_bounds__(512, 1)
void k_mma(const float* __restrict__ z) {
    extern __shared__ char smraw[];
    const uint32_t sb = smem_u32(smraw);
    const int tid  = threadIdx.x;
    const int lane = tid & 31;
    const int wid  = tid >> 5;           // 0..15
    const int mw   = wid >> 1;           // 0..7  (M-warp, 32 rows each)
    const int nw   = wid & 1;            // 0..1  (N-warp, 32 cols each)
    const int gid  = lane >> 2;
    const int tig  = lane & 3;
    const int row0 = blockIdx.x * BM;

    prefetchB(sb, tid, 0);
    asm volatile("cp.async.commit_group;" ::: "memory");

    // ---- prologue: z rows -> fp16 in smem, exact zn (reference rounding) ----
    if (tid < BM) {
        const float4* zr4 = (const float4*)(z + (size_t)(row0 + tid) * E_DIM);
        uint32_t* ap = (uint32_t*)(smraw + SM_A + (uint32_t)tid * ROWSTR);
        float zn = 0.0f;
        #pragma unroll 4
        for (int i = 0; i < 64; i++) {
            float4 v = zr4[i];
            zn = __fadd_rn(zn, __fmul_rn(v.x, v.x));
            zn = __fadd_rn(zn, __fmul_rn(v.y, v.y));
            zn = __fadd_rn(zn, __fmul_rn(v.z, v.z));
            zn = __fadd_rn(zn, __fmul_rn(v.w, v.w));
            __half h0 = __float2half_rn(v.x), h1 = __float2half_rn(v.y);
            __half h2 = __float2half_rn(v.z), h3 = __float2half_rn(v.w);
            ap[i * 2 + 0] = ((uint32_t)__half_as_ushort(h1) << 16) | __half_as_ushort(h0);
            ap[i * 2 + 1] = ((uint32_t)__half_as_ushort(h3) << 16) | __half_as_ushort(h2);
        }
        *(float*)(smraw + SM_ZN + tid * 4) = zn;
        g_zn[row0 + tid] = zn;
    }
    __syncthreads();

    // ldmatrix base addresses
    uint32_t aA[2], bA[2];
    {
        uint32_t arow = (uint32_t)(lane & 15);
        uint32_t ab   = ((uint32_t)(lane >> 4) & 1) * 16;
        #pragma unroll
        for (int mt = 0; mt < 2; mt++)
            aA[mt] = sb + SM_A + ((uint32_t)(mw * 32 + mt * 16) + arow) * ROWSTR + ab;
        #pragma unroll
        for (int p = 0; p < 2; p++)
            bA[p] = sb + SM_B + ((uint32_t)(nw * 32 + p * 16) + arow) * ROWSTR + ab;
    }

    float znv[4];
    #pragma unroll
    for (int sl = 0; sl < 4; sl++) {
        int r = mw * 32 + (sl >> 1) * 16 + (sl & 1) * 8 + gid;
        znv[sl] = *(const float*)(smraw + SM_ZN + r * 4);
    }

    float tb0[4], tb1[4];
    int   ti0[4], ti1[4];
    #pragma unroll
    for (int sl = 0; sl < 4; sl++) { tb0[sl] = 3.4e38f; tb1[sl] = 3.4e38f; ti0[sl] = 0; ti1[sl] = 0; }

    for (int nt = 0; nt < NSTG; nt++) {
        if (nt + 1 < NSTG) {
            prefetchB(sb, tid, nt + 1);
            asm volatile("cp.async.commit_group;" ::: "memory");
            asm volatile("cp.async.wait_group 1;" ::: "memory");
        } else {
            asm volatile("cp.async.wait_group 0;" ::: "memory");
        }
        __syncthreads();

        const uint32_t sof = (uint32_t)(nt & 1) * 33792u;
        uint32_t acc[2][4][2];            // f16x2 accumulators
        #pragma unroll
        for (int mt = 0; mt < 2; mt++)
            #pragma unroll
            for (int n2 = 0; n2 < 4; n2++) { acc[mt][n2][0] = 0u; acc[mt][n2][1] = 0u; }

        #pragma unroll
        for (int kk = 0; kk < 16; kk++) {
            uint32_t kb = (uint32_t)kk * 32;
            uint32_t af[2][4], bw[2][4];
            ldm4(af[0], aA[0] + kb);
            ldm4(af[1], aA[1] + kb);
            ldm4(bw[0], bA[0] + sof + kb);   // n-tiles 0,1: frags {r0,r2},{r1,r3}
            ldm4(bw[1], bA[1] + sof + kb);   // n-tiles 2,3
            #pragma unroll
            for (int mt = 0; mt < 2; mt++)
                #pragma unroll
                for (int p = 0; p < 2; p++)
                    #pragma unroll
                    for (int q = 0; q < 2; q++) {
                        uint32_t bf[2] = { bw[p][q], bw[p][q + 2] };
                        mma16816h(acc[mt][p * 2 + q], af[mt], bf);
                    }
        }

        // distances + per-slot top-2 (columns ascending)
        const float* eNs = (const float*)(smraw + SM_EN + (uint32_t)(nt & 1) * 256);
        #pragma unroll
        for (int n2 = 0; n2 < 4; n2++) {
            int colb = nt * BN + nw * 32 + n2 * 8 + 2 * tig;
            float e0 = eNs[nw * 32 + n2 * 8 + 2 * tig];
            float e1 = eNs[nw * 32 + n2 * 8 + 2 * tig + 1];
            #pragma unroll
            for (int mt = 0; mt < 2; mt++)
                #pragma unroll
                for (int hh = 0; hh < 2; hh++) {
                    int sl = mt * 2 + hh;
                    __half2 hv = *(__half2*)&acc[mt][n2][hh];
                    float dot0 = __half2float(__low2half(hv));
                    float dot1 = __half2float(__high2half(hv));
                    float d0 = __fmaf_rn(-2.0f, dot0, znv[sl] + e0);
                    float d1 = __fmaf_rn(-2.0f, dot1, znv[sl] + e1);
                    if (d0 < tb1[sl]) {
                        if (d0 < tb0[sl]) { tb1[sl]=tb0[sl]; ti1[sl]=ti0[sl]; tb0[sl]=d0; ti0[sl]=colb; }
                        else              { tb1[sl]=d0; ti1[sl]=colb; }
                    }
                    if (d1 < tb1[sl]) {
                        if (d1 < tb0[sl]) { tb1[sl]=tb0[sl]; ti1[sl]=ti0[sl]; tb0[sl]=d1; ti0[sl]=colb+1; }
                        else              { tb1[sl]=d1; ti1[sl]=colb+1; }
                    }
                }
        }
        __syncthreads();
    }

    // ---- candidate table in smem (reuse A region) ----
    float* tD = (float*)smraw;            // [256][16]
    int*   tI = (int*)(smraw + 16384);    // [256][16]
    #pragma unroll
    for (int sl = 0; sl < 4; sl++) {
        int r = mw * 32 + (sl >> 1) * 16 + (sl & 1) * 8 + gid;
        int owner = nw * 4 + tig;         // 0..7
        tD[r * 16 + owner * 2 + 0] = tb0[sl];
        tI[r * 16 + owner * 2 + 0] = ti0[sl];
        tD[r * 16 + owner * 2 + 1] = tb1[sl];
        tI[r * 16 + owner * 2 + 1] = ti1[sl];
    }
    __syncthreads();

    if (tid < BM) {
        float b0 = 3.4e38f, b1 = 3.4e38f;
        int   i0 = 0x7FFFFFFF, i1 = 0x7FFFFFFF;
        #pragma unroll
        for (int q = 0; q < 16; q++) {
            float d = tD[tid * 16 + q];
            int   c = tI[tid * 16 + q];
            if (d < b0 || (d == b0 && c < i0)) { b1 = b0; i1 = i0; b0 = d; i0 = c; }
            else if (d < b1 || (d == b1 && c < i1)) { b1 = d; i1 = c; }
        }
        int r = row0 + tid;
        g_idxi[r] = i0;
        if (__fsub_rn(b1, b0) < TH_MARGIN) {
            int u = atomicAdd(&g_ucount, 1);
            g_urows[u] = r;
            #pragma unroll
            for (int q = 0; q < 16; q++) g_ucand[u * 16 + q] = tI[tid * 16 + q];
        }
    }
}

// ============================================================
// K4: exact rescore of flagged rows (R0-identical numerics), 16 candidates
// ============================================================
__global__ void k_rescore(const float* __restrict__ z, const float* __restrict__ emb) {
    int t = blockIdx.x * blockDim.x + threadIdx.x;
    if (t >= g_ucount) return;
    int r = g_urows[t];
    const float* zr = z + (size_t)r * E_DIM;
    float zn = g_zn[r];
    float bd = 3.4e38f;
    int   bi = 0x7FFFFFFF;
    #pragma unroll 1
    for (int q = 0; q < 16; q++) {
        int c = g_ucand[t * 16 + q];
        const float* er = emb + (size_t)c * E_DIM;
        float acc = 0.0f;
        #pragma unroll 8
        for (int k = 0; k < E_DIM; k++) acc = __fmaf_rn(zr[k], er[k], acc);
        float d = __fsub_rn(__fadd_rn(zn, g_eN[c]), __fmul_rn(2.0f, acc));
        if (d < bd || (d == bd && c < bi)) { bd = d; bi = c; }
    }
    g_idxi[r] = bi;
}

// ============================================================
// K5: epilogue — z_q/straight-through, loss partials, bins/dw atomics
//   512 threads, 4 threads per row (64 floats each)
// ============================================================
__global__ __launch_bounds__(512)
void k_epi(const float* __restrict__ z, const float* __restrict__ emb,
           float* __restrict__ out_zq, float* __restrict__ out_idx) {
    __shared__ float sl[512];
    int tid = threadIdx.x;
    int row0 = blockIdx.x * 128;
    int r = row0 + (tid >> 2);
    int h = tid & 3;
    int bi = g_idxi[r];
    if (h == 0) { out_idx[r] = (float)bi; atomicAdd(&g_bins[bi], 1.0f); }
    const float4* zr = (const float4*)(z + (size_t)r * E_DIM + h * 64);
    const float4* er = (const float4*)(emb + (size_t)bi * E_DIM + h * 64);
    float4* oq = (float4*)(out_zq + (size_t)r * E_DIM + h * 64);
    float* dw = g_dw + (size_t)bi * E_DIM + h * 64;
    float ls = 0.0f;
    #pragma unroll 4
    for (int d4 = 0; d4 < 16; d4++) {
        float4 zv = zr[d4];
        float4 ev = er[d4];
        float4 o;
        o.x = __fadd_rn(zv.x, __fsub_rn(ev.x, zv.x));
        o.y = __fadd_rn(zv.y, __fsub_rn(ev.y, zv.y));
        o.z = __fadd_rn(zv.z, __fsub_rn(ev.z, zv.z));
        o.w = __fadd_rn(zv.w, __fsub_rn(ev.w, zv.w));
        oq[d4] = o;
        float dx = __fsub_rn(zv.x, ev.x);
        float dy = __fsub_rn(zv.y, ev.y);
        float dz = __fsub_rn(zv.z, ev.z);
        float dwv = __fsub_rn(zv.w, ev.w);
        ls = __fadd_rn(ls, __fmul_rn(dx, dx));
        ls = __fadd_rn(ls, __fmul_rn(dy, dy));
        ls = __fadd_rn(ls, __fmul_rn(dz, dz));
        ls = __fadd_rn(ls, __fmul_rn(dwv, dwv));
        atomicAdd(dw + d4 * 4 + 0, zv.x);
        atomicAdd(dw + d4 * 4 + 1, zv.y);
        atomicAdd(dw + d4 * 4 + 2, zv.z);
        atomicAdd(dw + d4 * 4 + 3, zv.w);
    }
    sl[tid] = ls;
    __syncthreads();
    for (int s = 256; s > 0; s >>= 1) {
        if (tid < s) sl[tid] += sl[tid + s];
        __syncthreads();
    }
    if (tid == 0) atomicAdd(&g_loss, sl[0]);
}

// ============================================================
// K6: finalize new_embeddings + loss
// ============================================================
__global__ void k_final(float* __restrict__ out_nemb, float* __restrict__ out_loss) {
    int gid = blockIdx.x * blockDim.x + threadIdx.x;
    if (gid == 0) {
        float mean = __fdiv_rn(g_loss, 8388608.0f);
        out_loss[0] = __fmul_rn(0.25f, mean);
    }
    if (gid < N_E * E_DIM) {
        int k = gid >> 8;
        float b = g_bins[k];
        float t1 = __fadd_rn(b, 1e-5f);
        float cl = __fmul_rn(__fdiv_rn(t1, 32768.08192f), 32768.0f);
        out_nemb[gid] = __fdiv_rn(g_dw[gid], cl);
    }
}

// ============================================================
extern "C" void kernel_launch(void* const* d_in, const int* in_sizes, int n_in,
                              void* d_out, int out_size) {
    const float* z   = (const float*)d_in[0];
    const float* emb = (const float*)d_in[1];
    float* out = (float*)d_out;

    cudaFuncSetAttribute(k_mma, cudaFuncAttributeMaxDynamicSharedMemorySize, SM_DYN);

    k_prep<<<8192, 256>>>(emb);
    k_mma<<<N_TOK / BM, 512, SM_DYN>>>(z);
    k_rescore<<<128, 256>>>(z, emb);
    k_epi<<<N_TOK / 128, 512>>>(z, emb, out + OFF_ZQ, out + OFF_IDX);
    k_final<<<8192, 256>>>(out + OFF_NEMB, out + OFF_LOSS);
}